// round 1
// baseline (speedup 1.0000x reference)
#include <cuda_runtime.h>

#define EPSV 1e-5f
#define RSQRT8 0.35355339059327373f

// scratch (allocation-free rule: device globals)
__device__ float g_q[4*512*64];
__device__ float g_k[4*512*64];
__device__ float g_v[4*512*64];

typedef unsigned long long ull;

__device__ __forceinline__ ull splat2(float x){
    ull r; unsigned u = __float_as_uint(x);
    asm("mov.b64 %0, {%1,%1};" : "=l"(r) : "r"(u));
    return r;
}
__device__ __forceinline__ void fma2a(ull& d, ull a, ull b){
    asm("fma.rn.f32x2 %0, %1, %2, %0;" : "+l"(d) : "l"(a), "l"(b));
}
__device__ __forceinline__ ull fma2g(ull a, ull b, ull c){
    ull d; asm("fma.rn.f32x2 %0, %1, %2, %3;" : "=l"(d) : "l"(a), "l"(b), "l"(c));
    return d;
}
__device__ __forceinline__ ull mul2(ull a, ull b){
    ull d; asm("mul.rn.f32x2 %0, %1, %2;" : "=l"(d) : "l"(a), "l"(b));
    return d;
}
__device__ __forceinline__ float2 unpack2(ull v){
    unsigned lo, hi;
    asm("mov.b64 {%0,%1}, %2;" : "=r"(lo), "=r"(hi) : "l"(v));
    return make_float2(__uint_as_float(lo), __uint_as_float(hi));
}
__device__ __forceinline__ void cpa16(void* sd, const void* g){
    unsigned s = (unsigned)__cvta_generic_to_shared(sd);
    asm volatile("cp.async.cg.shared.global [%0], [%1], 16;" :: "r"(s), "l"(g));
}

// ===================== Kernel 1: LN1 + QKV projection =====================
__global__ void qkv_kernel(const float* __restrict__ h, const float* __restrict__ Wh,
                           const float* __restrict__ g1, const float* __restrict__ b1)
{
    __shared__ float hn[64];
    __shared__ float part[4];
    int row = blockIdx.x, t = threadIdx.x;
    float x = h[row*64 + t];
    float s = x, q = x*x;
    #pragma unroll
    for (int o = 16; o >= 1; o >>= 1){
        s += __shfl_xor_sync(0xffffffffu, s, o);
        q += __shfl_xor_sync(0xffffffffu, q, o);
    }
    if ((t & 31) == 0){ part[t>>5] = s; part[2 + (t>>5)] = q; }
    __syncthreads();
    float mean = (part[0] + part[1]) * (1.f/64.f);
    float var  = (part[2] + part[3]) * (1.f/64.f) - mean*mean;
    float hv = (x - mean) * rsqrtf(var + EPSV) * g1[t] + b1[t];
    hn[t] = hv;
    __syncthreads();
    float aq = 0.f, ak = 0.f, av = 0.f;
    #pragma unroll 8
    for (int i = 0; i < 64; i++){
        float z = hn[i];
        aq = fmaf(z, Wh[i*192 + t],       aq);
        ak = fmaf(z, Wh[i*192 + 64 + t],  ak);
        av = fmaf(z, Wh[i*192 + 128 + t], av);
    }
    g_q[row*64 + t] = aq;
    g_k[row*64 + t] = ak;
    g_v[row*64 + t] = av;
}

// ===================== Kernel 2: fused edge-GEMM + attention + LN2 + MLP =====================
// Block: 128 threads = 4 warps. Warp w owns q-row q0+w (all 8 heads); lane = k within 32-wide tile.
// smem (floats):
//   e_s   [2][4*32][68]  = 17408
//   k_s   [2][32][68]    =  4352
//   v_s   [2][32][68]    =  4352
//   we_s  [64*16]        =  1024
//   y_s   [4*64]         =   256
//   z_s   [4*64]         =   256
//   hid_s [4*256]        =  1024
//   total 28672 floats   = 114688 B  -> 2 blocks/SM
__global__ void __launch_bounds__(128, 2)
attn_kernel(const float* __restrict__ e, const float* __restrict__ We,
            const float* __restrict__ hin, const float* __restrict__ w1,
            const float* __restrict__ w2, const float* __restrict__ g2,
            const float* __restrict__ b2, float* __restrict__ out)
{
    extern __shared__ float smem[];
    float* e_s   = smem;
    float* k_s   = smem + 17408;
    float* v_s   = smem + 21760;
    float* we_s  = smem + 26112;
    float* y_s   = smem + 27136;
    float* z_s   = smem + 27392;
    float* hid_s = smem + 27648;

    const int t    = threadIdx.x;
    const int w    = t >> 5;
    const int lane = t & 31;
    const int qt   = blockIdx.x;
    const int b    = qt >> 7;           // 128 q-tiles per batch
    const int q0   = (qt & 127) << 2;   // 4 q rows per tile

    const float* eg = e + ((size_t)(b*512 + q0)) * 512 * 64;
    const float* kg = g_k + (size_t)(b*512) * 64;
    const float* vg = g_v + (size_t)(b*512) * 64;

    // preload q row (64 floats as 32 packed pairs), uniform per warp
    ull qp[32];
    {
        const ull* qgp = (const ull*)(g_q + (size_t)(b*512 + q0 + w) * 64);
        #pragma unroll
        for (int i = 0; i < 32; i++) qp[i] = qgp[i];
    }

    // ---- issue tile 0 (+ W_e) into buffer 0 ----
    {
        #pragma unroll
        for (int it = 0; it < 16; it++){
            int f = t + it*128; int row = f >> 4, c = f & 15;
            int qq = row >> 5, kk = row & 31;
            cpa16(e_s + row*68 + c*4, eg + (size_t)qq*32768 + (size_t)kk*64 + c*4);
        }
        #pragma unroll
        for (int it = 0; it < 4; it++){
            int f = t + it*128; int row = f >> 4, c = f & 15;
            cpa16(k_s + row*68 + c*4, kg + (size_t)row*64 + c*4);
            cpa16(v_s + row*68 + c*4, vg + (size_t)row*64 + c*4);
        }
        #pragma unroll
        for (int it = 0; it < 2; it++){
            int f = t + it*128;
            cpa16(we_s + f*4, We + f*4);
        }
        asm volatile("cp.async.commit_group;");
    }

    float m[8], l[8];
    ull acc[32];
    #pragma unroll
    for (int hh = 0; hh < 8; hh++){ m[hh] = -1e30f; l[hh] = 0.f; }
    #pragma unroll
    for (int i = 0; i < 32; i++) acc[i] = 0ull;

    for (int tile = 0; tile < 16; tile++){
        const int buf = tile & 1;
        if (tile < 15){
            const int nb = (tile + 1) & 1;
            const int k0 = (tile + 1) * 32;
            float* ed = e_s + nb*8704;
            float* kd = k_s + nb*2176;
            float* vd = v_s + nb*2176;
            #pragma unroll
            for (int it = 0; it < 16; it++){
                int f = t + it*128; int row = f >> 4, c = f & 15;
                int qq = row >> 5, kk = row & 31;
                cpa16(ed + row*68 + c*4, eg + (size_t)qq*32768 + (size_t)(k0+kk)*64 + c*4);
            }
            #pragma unroll
            for (int it = 0; it < 4; it++){
                int f = t + it*128; int row = f >> 4, c = f & 15;
                cpa16(kd + row*68 + c*4, kg + (size_t)(k0+row)*64 + c*4);
                cpa16(vd + row*68 + c*4, vg + (size_t)(k0+row)*64 + c*4);
            }
            asm volatile("cp.async.commit_group;");
            asm volatile("cp.async.wait_group 1;");
        } else {
            asm volatile("cp.async.wait_group 0;");
        }
        __syncthreads();

        // ---- ew = e_row . W_e  (16 outputs, packed f32x2 FMA) ----
        const float4* erow = (const float4*)(e_s + buf*8704 + (w*32 + lane)*68);
        const ull* weP = (const ull*)we_s;
        ull ew[8];
        #pragma unroll
        for (int p = 0; p < 8; p++) ew[p] = 0ull;
        #pragma unroll
        for (int i4 = 0; i4 < 16; i4++){
            float4 ev = erow[i4];
            float evv[4] = {ev.x, ev.y, ev.z, ev.w};
            #pragma unroll
            for (int c = 0; c < 4; c++){
                ull es = splat2(evv[c]);
                const ull* wr = weP + (i4*4 + c)*8;
                #pragma unroll
                for (int p = 0; p < 8; p++) fma2a(ew[p], es, wr[p]);
            }
        }
        float e1[8], e2v[8];
        #pragma unroll
        for (int p = 0; p < 4; p++){ float2 u = unpack2(ew[p]);   e1[2*p] = u.x;  e1[2*p+1] = u.y; }
        #pragma unroll
        for (int p = 0; p < 4; p++){ float2 u = unpack2(ew[4+p]); e2v[2*p] = u.x; e2v[2*p+1] = u.y; }

        // ---- per-head: logit, online softmax (lane-local), gated PV accumulate ----
        const ulonglong2* kr = (const ulonglong2*)(k_s + buf*2176 + lane*68);
        const ulonglong2* vr = (const ulonglong2*)(v_s + buf*2176 + lane*68);
        #pragma unroll
        for (int hh = 0; hh < 8; hh++){
            ulonglong2 ka = kr[2*hh], kb = kr[2*hh+1];
            ull s2 = mul2(qp[4*hh], ka.x);
            fma2a(s2, qp[4*hh+1], ka.y);
            fma2a(s2, qp[4*hh+2], kb.x);
            fma2a(s2, qp[4*hh+3], kb.y);
            float2 sp = unpack2(s2);
            float s = fmaf(sp.x + sp.y, RSQRT8, e1[hh]);
            float mn = fmaxf(m[hh], s);
            float sc = __expf(m[hh] - mn);
            float p  = __expf(s - mn);
            l[hh] = fmaf(l[hh], sc, p);
            m[hh] = mn;
            float g = p * e2v[hh];
            ull gg = splat2(g), sc2 = splat2(sc);
            ulonglong2 va = vr[2*hh], vb = vr[2*hh+1];
            acc[4*hh+0] = fma2g(acc[4*hh+0], sc2, mul2(gg, va.x));
            acc[4*hh+1] = fma2g(acc[4*hh+1], sc2, mul2(gg, va.y));
            acc[4*hh+2] = fma2g(acc[4*hh+2], sc2, mul2(gg, vb.x));
            acc[4*hh+3] = fma2g(acc[4*hh+3], sc2, mul2(gg, vb.y));
        }
        __syncthreads();
    }

    // ---- cross-lane butterfly merge of (m, l, acc) ----
    #pragma unroll
    for (int off = 16; off >= 1; off >>= 1){
        #pragma unroll
        for (int hh = 0; hh < 8; hh++){
            float mo = __shfl_xor_sync(0xffffffffu, m[hh], off);
            float lo = __shfl_xor_sync(0xffffffffu, l[hh], off);
            ull a0 = __shfl_xor_sync(0xffffffffu, acc[4*hh+0], off);
            ull a1 = __shfl_xor_sync(0xffffffffu, acc[4*hh+1], off);
            ull a2 = __shfl_xor_sync(0xffffffffu, acc[4*hh+2], off);
            ull a3 = __shfl_xor_sync(0xffffffffu, acc[4*hh+3], off);
            float mn = fmaxf(m[hh], mo);
            float sa = __expf(m[hh] - mn), sb = __expf(mo - mn);
            l[hh] = l[hh]*sa + lo*sb;
            ull sa2 = splat2(sa), sb2 = splat2(sb);
            acc[4*hh+0] = fma2g(acc[4*hh+0], sa2, mul2(a0, sb2));
            acc[4*hh+1] = fma2g(acc[4*hh+1], sa2, mul2(a1, sb2));
            acc[4*hh+2] = fma2g(acc[4*hh+2], sa2, mul2(a2, sb2));
            acc[4*hh+3] = fma2g(acc[4*hh+3], sa2, mul2(a3, sb2));
            m[hh] = mn;
        }
    }

    if (lane == 0){
        #pragma unroll
        for (int hh = 0; hh < 8; hh++){
            float inv = __fdividef(1.f, l[hh]);
            #pragma unroll
            for (int d2 = 0; d2 < 4; d2++){
                float2 u = unpack2(acc[4*hh + d2]);
                y_s[w*64 + hh*8 + d2*2]     = u.x * inv;
                y_s[w*64 + hh*8 + d2*2 + 1] = u.y * inv;
            }
        }
    }
    __syncthreads();

    // ---- LN2 over (y + h_in), per-row (warp w = row w) ----
    {
        const float* hrow = hin + (size_t)(b*512 + q0 + w) * 64;
        float x0 = y_s[w*64 + lane]      + hrow[lane];
        float x1 = y_s[w*64 + lane + 32] + hrow[lane + 32];
        float s = x0 + x1, sq = x0*x0 + x1*x1;
        #pragma unroll
        for (int o = 16; o >= 1; o >>= 1){
            s  += __shfl_xor_sync(0xffffffffu, s, o);
            sq += __shfl_xor_sync(0xffffffffu, sq, o);
        }
        float mean = s * (1.f/64.f);
        float var  = sq * (1.f/64.f) - mean*mean;
        float rs = rsqrtf(var + EPSV);
        z_s[w*64 + lane]      = (x0 - mean) * rs * g2[lane]      + b2[lane];
        z_s[w*64 + lane + 32] = (x1 - mean) * rs * g2[lane + 32] + b2[lane + 32];
    }
    __syncthreads();

    // ---- hidden = relu(z @ w1)  [4 x 256] ----
    #pragma unroll
    for (int jj = t; jj < 256; jj += 128){
        float a0 = 0.f, a1 = 0.f, a2 = 0.f, a3 = 0.f;
        #pragma unroll 8
        for (int i = 0; i < 64; i++){
            float wv = w1[i*256 + jj];
            a0 = fmaf(z_s[i],       wv, a0);
            a1 = fmaf(z_s[64 + i],  wv, a1);
            a2 = fmaf(z_s[128 + i], wv, a2);
            a3 = fmaf(z_s[192 + i], wv, a3);
        }
        hid_s[jj]       = fmaxf(a0, 0.f);
        hid_s[256 + jj] = fmaxf(a1, 0.f);
        hid_s[512 + jj] = fmaxf(a2, 0.f);
        hid_s[768 + jj] = fmaxf(a3, 0.f);
    }
    __syncthreads();

    // ---- out = hidden @ w2 + y ----
    {
        int d = t & 63, r0 = t >> 6;   // rows r0 and r0+2
        float a0 = 0.f, a1 = 0.f;
        #pragma unroll 8
        for (int j = 0; j < 256; j++){
            float wv = w2[j*64 + d];
            a0 = fmaf(hid_s[r0*256 + j],     wv, a0);
            a1 = fmaf(hid_s[(r0+2)*256 + j], wv, a1);
        }
        out[((size_t)(b*512 + q0 + r0)) * 64 + d]     = a0 + y_s[r0*64 + d];
        out[((size_t)(b*512 + q0 + r0 + 2)) * 64 + d] = a1 + y_s[(r0+2)*64 + d];
    }
}

extern "C" void kernel_launch(void* const* d_in, const int* in_sizes, int n_in,
                              void* d_out, int out_size)
{
    const float* h  = (const float*)d_in[0];
    const float* e  = (const float*)d_in[1];
    const float* Wh = (const float*)d_in[2];
    const float* We = (const float*)d_in[3];
    const float* w1 = (const float*)d_in[4];
    const float* w2 = (const float*)d_in[5];
    const float* g1 = (const float*)d_in[6];
    const float* b1 = (const float*)d_in[7];
    const float* g2 = (const float*)d_in[8];
    const float* b2 = (const float*)d_in[9];
    float* out = (float*)d_out;

    cudaFuncSetAttribute(attn_kernel, cudaFuncAttributeMaxDynamicSharedMemorySize, 114688);

    qkv_kernel<<<2048, 64>>>(h, Wh, g1, b1);
    attn_kernel<<<512, 128, 114688>>>(e, We, h, w1, w2, g2, b2, out);
}

// round 2
// speedup vs baseline: 1.0002x; 1.0002x over previous
#include <cuda_runtime.h>

#define EPSV 1e-5f
#define RSQRT8 0.35355339059327373f

// scratch (allocation-free rule: device globals)
__device__ float g_q[4*512*64];
__device__ float g_k[4*512*64];
__device__ float g_v[4*512*64];

typedef unsigned long long ull;

__device__ __forceinline__ ull splat2(float x){
    ull r; unsigned u = __float_as_uint(x);
    asm("mov.b64 %0, {%1,%1};" : "=l"(r) : "r"(u));
    return r;
}
__device__ __forceinline__ void fma2a(ull& d, ull a, ull b){
    asm("fma.rn.f32x2 %0, %1, %2, %0;" : "+l"(d) : "l"(a), "l"(b));
}
__device__ __forceinline__ ull fma2g(ull a, ull b, ull c){
    ull d; asm("fma.rn.f32x2 %0, %1, %2, %3;" : "=l"(d) : "l"(a), "l"(b), "l"(c));
    return d;
}
__device__ __forceinline__ ull mul2(ull a, ull b){
    ull d; asm("mul.rn.f32x2 %0, %1, %2;" : "=l"(d) : "l"(a), "l"(b));
    return d;
}
__device__ __forceinline__ float2 unpack2(ull v){
    unsigned lo, hi;
    asm("mov.b64 {%0,%1}, %2;" : "=r"(lo), "=r"(hi) : "l"(v));
    return make_float2(__uint_as_float(lo), __uint_as_float(hi));
}
__device__ __forceinline__ void cpa16(void* sd, const void* g){
    unsigned s = (unsigned)__cvta_generic_to_shared(sd);
    asm volatile("cp.async.cg.shared.global [%0], [%1], 16;" :: "r"(s), "l"(g));
}

// ===================== Kernel 1: LN1 + QKV projection =====================
__global__ void qkv_kernel(const float* __restrict__ h, const float* __restrict__ Wh,
                           const float* __restrict__ g1, const float* __restrict__ b1)
{
    __shared__ float hn[64];
    __shared__ float part[4];
    int row = blockIdx.x, t = threadIdx.x;
    float x = h[row*64 + t];
    float s = x, q = x*x;
    #pragma unroll
    for (int o = 16; o >= 1; o >>= 1){
        s += __shfl_xor_sync(0xffffffffu, s, o);
        q += __shfl_xor_sync(0xffffffffu, q, o);
    }
    if ((t & 31) == 0){ part[t>>5] = s; part[2 + (t>>5)] = q; }
    __syncthreads();
    float mean = (part[0] + part[1]) * (1.f/64.f);
    float var  = (part[2] + part[3]) * (1.f/64.f) - mean*mean;
    float hv = (x - mean) * rsqrtf(var + EPSV) * g1[t] + b1[t];
    hn[t] = hv;
    __syncthreads();
    float aq = 0.f, ak = 0.f, av = 0.f;
    #pragma unroll 8
    for (int i = 0; i < 64; i++){
        float z = hn[i];
        aq = fmaf(z, Wh[i*192 + t],       aq);
        ak = fmaf(z, Wh[i*192 + 64 + t],  ak);
        av = fmaf(z, Wh[i*192 + 128 + t], av);
    }
    g_q[row*64 + t] = aq;
    g_k[row*64 + t] = ak;
    g_v[row*64 + t] = av;
}

// ===================== Kernel 2: fused edge-GEMM + attention + LN2 + MLP =====================
// Block: 128 threads = 4 warps. Warp w owns q-row q0+w (all 8 heads); lane = k within 32-wide tile.
// smem (floats):
//   e_s   [2][4*32][68]  = 17408
//   k_s   [2][32][68]    =  4352
//   v_s   [2][32][68]    =  4352
//   we_s  [64*16]        =  1024
//   y_s   [4*64]         =   256
//   z_s   [4*64]         =   256
//   hid_s [4*256]        =  1024
//   total 28672 floats   = 114688 B  -> 2 blocks/SM
__global__ void __launch_bounds__(128, 2)
attn_kernel(const float* __restrict__ e, const float* __restrict__ We,
            const float* __restrict__ hin, const float* __restrict__ w1,
            const float* __restrict__ w2, const float* __restrict__ g2,
            const float* __restrict__ b2, float* __restrict__ out)
{
    extern __shared__ float smem[];
    float* e_s   = smem;
    float* k_s   = smem + 17408;
    float* v_s   = smem + 21760;
    float* we_s  = smem + 26112;
    float* y_s   = smem + 27136;
    float* z_s   = smem + 27392;
    float* hid_s = smem + 27648;

    const int t    = threadIdx.x;
    const int w    = t >> 5;
    const int lane = t & 31;
    const int qt   = blockIdx.x;
    const int b    = qt >> 7;           // 128 q-tiles per batch
    const int q0   = (qt & 127) << 2;   // 4 q rows per tile

    const float* eg = e + ((size_t)(b*512 + q0)) * 512 * 64;
    const float* kg = g_k + (size_t)(b*512) * 64;
    const float* vg = g_v + (size_t)(b*512) * 64;

    // preload q row (64 floats as 32 packed pairs), uniform per warp
    ull qp[32];
    {
        const ull* qgp = (const ull*)(g_q + (size_t)(b*512 + q0 + w) * 64);
        #pragma unroll
        for (int i = 0; i < 32; i++) qp[i] = qgp[i];
    }

    // ---- issue tile 0 (+ W_e) into buffer 0 ----
    {
        #pragma unroll
        for (int it = 0; it < 16; it++){
            int f = t + it*128; int row = f >> 4, c = f & 15;
            int qq = row >> 5, kk = row & 31;
            cpa16(e_s + row*68 + c*4, eg + (size_t)qq*32768 + (size_t)kk*64 + c*4);
        }
        #pragma unroll
        for (int it = 0; it < 4; it++){
            int f = t + it*128; int row = f >> 4, c = f & 15;
            cpa16(k_s + row*68 + c*4, kg + (size_t)row*64 + c*4);
            cpa16(v_s + row*68 + c*4, vg + (size_t)row*64 + c*4);
        }
        #pragma unroll
        for (int it = 0; it < 2; it++){
            int f = t + it*128;
            cpa16(we_s + f*4, We + f*4);
        }
        asm volatile("cp.async.commit_group;");
    }

    float m[8], l[8];
    ull acc[32];
    #pragma unroll
    for (int hh = 0; hh < 8; hh++){ m[hh] = -1e30f; l[hh] = 0.f; }
    #pragma unroll
    for (int i = 0; i < 32; i++) acc[i] = 0ull;

    for (int tile = 0; tile < 16; tile++){
        const int buf = tile & 1;
        if (tile < 15){
            const int nb = (tile + 1) & 1;
            const int k0 = (tile + 1) * 32;
            float* ed = e_s + nb*8704;
            float* kd = k_s + nb*2176;
            float* vd = v_s + nb*2176;
            #pragma unroll
            for (int it = 0; it < 16; it++){
                int f = t + it*128; int row = f >> 4, c = f & 15;
                int qq = row >> 5, kk = row & 31;
                cpa16(ed + row*68 + c*4, eg + (size_t)qq*32768 + (size_t)(k0+kk)*64 + c*4);
            }
            #pragma unroll
            for (int it = 0; it < 4; it++){
                int f = t + it*128; int row = f >> 4, c = f & 15;
                cpa16(kd + row*68 + c*4, kg + (size_t)(k0+row)*64 + c*4);
                cpa16(vd + row*68 + c*4, vg + (size_t)(k0+row)*64 + c*4);
            }
            asm volatile("cp.async.commit_group;");
            asm volatile("cp.async.wait_group 1;");
        } else {
            asm volatile("cp.async.wait_group 0;");
        }
        __syncthreads();

        // ---- ew = e_row . W_e  (16 outputs, packed f32x2 FMA) ----
        const float4* erow = (const float4*)(e_s + buf*8704 + (w*32 + lane)*68);
        const ull* weP = (const ull*)we_s;
        ull ew[8];
        #pragma unroll
        for (int p = 0; p < 8; p++) ew[p] = 0ull;
        #pragma unroll
        for (int i4 = 0; i4 < 16; i4++){
            float4 ev = erow[i4];
            float evv[4] = {ev.x, ev.y, ev.z, ev.w};
            #pragma unroll
            for (int c = 0; c < 4; c++){
                ull es = splat2(evv[c]);
                const ull* wr = weP + (i4*4 + c)*8;
                #pragma unroll
                for (int p = 0; p < 8; p++) fma2a(ew[p], es, wr[p]);
            }
        }
        float e1[8], e2v[8];
        #pragma unroll
        for (int p = 0; p < 4; p++){ float2 u = unpack2(ew[p]);   e1[2*p] = u.x;  e1[2*p+1] = u.y; }
        #pragma unroll
        for (int p = 0; p < 4; p++){ float2 u = unpack2(ew[4+p]); e2v[2*p] = u.x; e2v[2*p+1] = u.y; }

        // ---- per-head: logit, online softmax (lane-local), gated PV accumulate ----
        const ulonglong2* kr = (const ulonglong2*)(k_s + buf*2176 + lane*68);
        const ulonglong2* vr = (const ulonglong2*)(v_s + buf*2176 + lane*68);
        #pragma unroll
        for (int hh = 0; hh < 8; hh++){
            ulonglong2 ka = kr[2*hh], kb = kr[2*hh+1];
            ull s2 = mul2(qp[4*hh], ka.x);
            fma2a(s2, qp[4*hh+1], ka.y);
            fma2a(s2, qp[4*hh+2], kb.x);
            fma2a(s2, qp[4*hh+3], kb.y);
            float2 sp = unpack2(s2);
            float s = fmaf(sp.x + sp.y, RSQRT8, e1[hh]);
            float mn = fmaxf(m[hh], s);
            float sc = __expf(m[hh] - mn);
            float p  = __expf(s - mn);
            l[hh] = fmaf(l[hh], sc, p);
            m[hh] = mn;
            float g = p * e2v[hh];
            ull gg = splat2(g), sc2 = splat2(sc);
            ulonglong2 va = vr[2*hh], vb = vr[2*hh+1];
            acc[4*hh+0] = fma2g(acc[4*hh+0], sc2, mul2(gg, va.x));
            acc[4*hh+1] = fma2g(acc[4*hh+1], sc2, mul2(gg, va.y));
            acc[4*hh+2] = fma2g(acc[4*hh+2], sc2, mul2(gg, vb.x));
            acc[4*hh+3] = fma2g(acc[4*hh+3], sc2, mul2(gg, vb.y));
        }
        __syncthreads();
    }

    // ---- cross-lane butterfly merge of (m, l, acc) ----
    #pragma unroll
    for (int off = 16; off >= 1; off >>= 1){
        #pragma unroll
        for (int hh = 0; hh < 8; hh++){
            float mo = __shfl_xor_sync(0xffffffffu, m[hh], off);
            float lo = __shfl_xor_sync(0xffffffffu, l[hh], off);
            ull a0 = __shfl_xor_sync(0xffffffffu, acc[4*hh+0], off);
            ull a1 = __shfl_xor_sync(0xffffffffu, acc[4*hh+1], off);
            ull a2 = __shfl_xor_sync(0xffffffffu, acc[4*hh+2], off);
            ull a3 = __shfl_xor_sync(0xffffffffu, acc[4*hh+3], off);
            float mn = fmaxf(m[hh], mo);
            float sa = __expf(m[hh] - mn), sb = __expf(mo - mn);
            l[hh] = l[hh]*sa + lo*sb;
            ull sa2 = splat2(sa), sb2 = splat2(sb);
            acc[4*hh+0] = fma2g(acc[4*hh+0], sa2, mul2(a0, sb2));
            acc[4*hh+1] = fma2g(acc[4*hh+1], sa2, mul2(a1, sb2));
            acc[4*hh+2] = fma2g(acc[4*hh+2], sa2, mul2(a2, sb2));
            acc[4*hh+3] = fma2g(acc[4*hh+3], sa2, mul2(a3, sb2));
            m[hh] = mn;
        }
    }

    if (lane == 0){
        #pragma unroll
        for (int hh = 0; hh < 8; hh++){
            float inv = __fdividef(1.f, l[hh]);
            #pragma unroll
            for (int d2 = 0; d2 < 4; d2++){
                float2 u = unpack2(acc[4*hh + d2]);
                y_s[w*64 + hh*8 + d2*2]     = u.x * inv;
                y_s[w*64 + hh*8 + d2*2 + 1] = u.y * inv;
            }
        }
    }
    __syncthreads();

    // ---- LN2 over (y + h_in), per-row (warp w = row w) ----
    {
        const float* hrow = hin + (size_t)(b*512 + q0 + w) * 64;
        float x0 = y_s[w*64 + lane]      + hrow[lane];
        float x1 = y_s[w*64 + lane + 32] + hrow[lane + 32];
        float s = x0 + x1, sq = x0*x0 + x1*x1;
        #pragma unroll
        for (int o = 16; o >= 1; o >>= 1){
            s  += __shfl_xor_sync(0xffffffffu, s, o);
            sq += __shfl_xor_sync(0xffffffffu, sq, o);
        }
        float mean = s * (1.f/64.f);
        float var  = sq * (1.f/64.f) - mean*mean;
        float rs = rsqrtf(var + EPSV);
        z_s[w*64 + lane]      = (x0 - mean) * rs * g2[lane]      + b2[lane];
        z_s[w*64 + lane + 32] = (x1 - mean) * rs * g2[lane + 32] + b2[lane + 32];
    }
    __syncthreads();

    // ---- hidden = relu(z @ w1)  [4 x 256] ----
    #pragma unroll
    for (int jj = t; jj < 256; jj += 128){
        float a0 = 0.f, a1 = 0.f, a2 = 0.f, a3 = 0.f;
        #pragma unroll 8
        for (int i = 0; i < 64; i++){
            float wv = w1[i*256 + jj];
            a0 = fmaf(z_s[i],       wv, a0);
            a1 = fmaf(z_s[64 + i],  wv, a1);
            a2 = fmaf(z_s[128 + i], wv, a2);
            a3 = fmaf(z_s[192 + i], wv, a3);
        }
        hid_s[jj]       = fmaxf(a0, 0.f);
        hid_s[256 + jj] = fmaxf(a1, 0.f);
        hid_s[512 + jj] = fmaxf(a2, 0.f);
        hid_s[768 + jj] = fmaxf(a3, 0.f);
    }
    __syncthreads();

    // ---- out = hidden @ w2 + y ----
    {
        int d = t & 63, r0 = t >> 6;   // rows r0 and r0+2
        float a0 = 0.f, a1 = 0.f;
        #pragma unroll 8
        for (int j = 0; j < 256; j++){
            float wv = w2[j*64 + d];
            a0 = fmaf(hid_s[r0*256 + j],     wv, a0);
            a1 = fmaf(hid_s[(r0+2)*256 + j], wv, a1);
        }
        out[((size_t)(b*512 + q0 + r0)) * 64 + d]     = a0 + y_s[r0*64 + d];
        out[((size_t)(b*512 + q0 + r0 + 2)) * 64 + d] = a1 + y_s[(r0+2)*64 + d];
    }
}

extern "C" void kernel_launch(void* const* d_in, const int* in_sizes, int n_in,
                              void* d_out, int out_size)
{
    const float* h  = (const float*)d_in[0];
    const float* e  = (const float*)d_in[1];
    const float* Wh = (const float*)d_in[2];
    const float* We = (const float*)d_in[3];
    const float* w1 = (const float*)d_in[4];
    const float* w2 = (const float*)d_in[5];
    const float* g1 = (const float*)d_in[6];
    const float* b1 = (const float*)d_in[7];
    const float* g2 = (const float*)d_in[8];
    const float* b2 = (const float*)d_in[9];
    float* out = (float*)d_out;

    cudaFuncSetAttribute(attn_kernel, cudaFuncAttributeMaxDynamicSharedMemorySize, 114688);

    qkv_kernel<<<2048, 64>>>(h, Wh, g1, b1);
    attn_kernel<<<512, 128, 114688>>>(e, We, h, w1, w2, g2, b2, out);
}